// round 2
// baseline (speedup 1.0000x reference)
#include <cuda_runtime.h>
#include <cuda_fp16.h>
#include <cstdint>

// ============================================================================
// IWConLoss on GB300 (sm_103a via compute_103 baseline PTX):
//   scores = Q @ Neg^T / tau ; loss = mean( LSE_row(scores) - (Q.P)/tau )
// Tensor path: ldmatrix + mma.sync.m16n8k16 (fp16 in, fp32 acc).
// Q is pre-scaled by log2(e)/tau so GEMM emits log2-domain logits directly.
// pos logit computed exactly in fp32. Online log2-domain LSE in registers.
// ============================================================================

static constexpr int NQ   = 8192;
static constexpr int NNEG = 16384;
static constexpr int KD   = 128;

static constexpr int MB = 128;     // query rows per CTA
static constexpr int NT = 128;     // negatives per tile
static constexpr int SPLITS = 2;   // neg splits -> grid 64 x 2 = 128 CTAs
static constexpr int TILES = NNEG / SPLITS / NT;   // 64
static constexpr int STAGES = 4;

static constexpr int PITCH = 272;                    // bytes per row: 128 fp16 + 8 pad
static constexpr int TILE_BYTES = 128 * PITCH;       // 34816
static constexpr int SMEM_TOTAL = TILE_BYTES * (1 + STAGES);  // Q + 4 stages = 174080

static constexpr float INV_TAU = 5.0f;                 // 1/0.2
static constexpr float C_T  = 7.2134752044448170f;     // log2(e)/tau
static constexpr float LN2F = 0.69314718055994531f;

// ---------------- device scratch (no allocs allowed) ----------------
__device__ __align__(16) __half g_qh[NQ * KD];     // Q * C_T, fp16
__device__ __align__(16) __half g_nh[NNEG * KD];   // Neg, fp16
__device__ float g_poslogit[NQ];
__device__ float g_pm[NQ * SPLITS];
__device__ float g_ps[NQ * SPLITS];

// ---------------- helpers ----------------
__device__ __forceinline__ uint32_t smem_u32(const void* p) {
    uint32_t a;
    asm("{ .reg .u64 t; cvta.to.shared.u64 t, %1; cvt.u32.u64 %0, t; }"
        : "=r"(a) : "l"(p));
    return a;
}
__device__ __forceinline__ float ex2f(float x) {
    float r; asm("ex2.approx.ftz.f32 %0, %1;" : "=f"(r) : "f"(x)); return r;
}
__device__ __forceinline__ void cpa16(uint32_t dst, const void* src) {
    asm volatile("cp.async.cg.shared.global [%0], [%1], 16;" :: "r"(dst), "l"(src));
}
#define CP_COMMIT() asm volatile("cp.async.commit_group;" ::: "memory")
#define CP_WAIT(n)  asm volatile("cp.async.wait_group %0;" :: "n"(n) : "memory")

__device__ __forceinline__ void ldsm4(uint32_t& r0, uint32_t& r1, uint32_t& r2,
                                      uint32_t& r3, uint32_t addr) {
    asm volatile("ldmatrix.sync.aligned.m8n8.x4.shared.b16 {%0,%1,%2,%3}, [%4];"
        : "=r"(r0), "=r"(r1), "=r"(r2), "=r"(r3) : "r"(addr));
}
__device__ __forceinline__ void mma16816(float* d, const uint32_t* a,
                                         const uint32_t b0, const uint32_t b1) {
    asm volatile(
        "mma.sync.aligned.m16n8k16.row.col.f32.f16.f16.f32 "
        "{%0,%1,%2,%3}, {%4,%5,%6,%7}, {%8,%9}, {%0,%1,%2,%3};"
        : "+f"(d[0]), "+f"(d[1]), "+f"(d[2]), "+f"(d[3])
        : "r"(a[0]), "r"(a[1]), "r"(a[2]), "r"(a[3]), "r"(b0), "r"(b1));
}

// ============================================================================
// prep kernels
// ============================================================================
__global__ void prep_neg_kernel(const float* __restrict__ neg) {
    int i = (blockIdx.x * 256 + threadIdx.x) * 4;
    float4 v = *reinterpret_cast<const float4*>(neg + i);
    __half2* o = reinterpret_cast<__half2*>(g_nh + i);
    o[0] = __floats2half2_rn(v.x, v.y);
    o[1] = __floats2half2_rn(v.z, v.w);
}

__global__ void prep_q_kernel(const float* __restrict__ q, const float* __restrict__ pos) {
    int w = threadIdx.x >> 5, lane = threadIdx.x & 31;
    int row = blockIdx.x * 8 + w;
    const float4 q4 = *reinterpret_cast<const float4*>(q + row * KD + lane * 4);
    const float4 p4 = *reinterpret_cast<const float4*>(pos + row * KD + lane * 4);
    float d = q4.x * p4.x + q4.y * p4.y + q4.z * p4.z + q4.w * p4.w;
    #pragma unroll
    for (int o = 16; o > 0; o >>= 1) d += __shfl_xor_sync(0xffffffffu, d, o);
    if (lane == 0) g_poslogit[row] = d * INV_TAU;

    __half2* o = reinterpret_cast<__half2*>(g_qh + row * KD + lane * 4);
    o[0] = __floats2half2_rn(q4.x * C_T, q4.y * C_T);
    o[1] = __floats2half2_rn(q4.z * C_T, q4.w * C_T);
}

// ============================================================================
// main fused kernel: GEMM (mma.sync) + online LSE
// ============================================================================
__device__ __forceinline__ void copy_q_block(uint32_t sb, int tid, int qbase) {
    #pragma unroll
    for (int j = 0; j < 8; j++) {
        int idx = j * 256 + tid;             // 0..2047
        int row = idx >> 4, c = idx & 15;
        uint32_t dst = sb + (uint32_t)(row * PITCH + c * 16);
        cpa16(dst, g_qh + (qbase + row) * KD + c * 8);
    }
}
__device__ __forceinline__ void copy_neg_tile(uint32_t sb, int tid, int stage, int rowbase) {
    uint32_t base = sb + (uint32_t)(TILE_BYTES * (1 + stage));
    #pragma unroll
    for (int j = 0; j < 8; j++) {
        int idx = j * 256 + tid;
        int row = idx >> 4, c = idx & 15;
        cpa16(base + (uint32_t)(row * PITCH + c * 16),
              g_nh + (rowbase + row) * KD + c * 8);
    }
}

__global__ __launch_bounds__(256, 1) void conloss_main_kernel() {
    extern __shared__ char smem[];
    uint32_t sb = smem_u32(smem);
    const int tid = threadIdx.x, warp = tid >> 5, lane = tid & 31;
    const int wm = warp & 1;          // 2 warp-rows of 64
    const int wn = warp >> 1;         // 4 warp-cols of 32
    const int qbase = blockIdx.x * MB;
    const int negbase = blockIdx.y * (NNEG / SPLITS);

    // prologue: Q + first STAGES neg tiles
    copy_q_block(sb, tid, qbase);
    copy_neg_tile(sb, tid, 0, negbase);
    CP_COMMIT();                           // group 0: Q + tile0
    #pragma unroll
    for (int s2 = 1; s2 < STAGES; s2++) {
        copy_neg_tile(sb, tid, s2, negbase + s2 * NT);
        CP_COMMIT();
    }

    // ldmatrix base addresses
    // A (Q): rows = wm*64 + mi*16 + (lane&15); k-byte = (lane>>4)*16 (+ks*32)
    const uint32_t aBase = sb + (uint32_t)((wm * 64 + (lane & 15)) * PITCH + ((lane >> 4) * 16));
    // B (Neg): n = wn*32 + np*16 + (lane&7) + (lane>>4)*8 ; k-byte = ((lane>>3)&1)*16
    const uint32_t bOff = (uint32_t)(((wn * 32) + (lane & 7) + ((lane >> 4) << 3)) * PITCH
                                     + (((lane >> 3) & 1) * 16));

    float C[4][4][4];
    float mrun[8], srun[8];
    #pragma unroll
    for (int j = 0; j < 8; j++) { mrun[j] = -1e30f; srun[j] = 0.0f; }

    for (int t = 0; t < TILES; t++) {
        CP_WAIT(STAGES - 1);
        __syncthreads();

        #pragma unroll
        for (int mi = 0; mi < 4; mi++)
            #pragma unroll
            for (int ni = 0; ni < 4; ni++)
                #pragma unroll
                for (int r = 0; r < 4; r++) C[mi][ni][r] = 0.0f;

        const uint32_t bBase = sb + (uint32_t)(TILE_BYTES * (1 + (t % STAGES))) + bOff;

        #pragma unroll
        for (int ks = 0; ks < 8; ks++) {
            uint32_t A[4][4], B[2][4];
            #pragma unroll
            for (int mi = 0; mi < 4; mi++)
                ldsm4(A[mi][0], A[mi][1], A[mi][2], A[mi][3],
                      aBase + (uint32_t)(mi * 16 * PITCH + ks * 32));
            #pragma unroll
            for (int np = 0; np < 2; np++)
                ldsm4(B[np][0], B[np][1], B[np][2], B[np][3],
                      bBase + (uint32_t)(np * 16 * PITCH + ks * 32));
            #pragma unroll
            for (int mi = 0; mi < 4; mi++)
                #pragma unroll
                for (int ni = 0; ni < 4; ni++)
                    mma16816(C[mi][ni], A[mi],
                             B[ni >> 1][(ni & 1) * 2], B[ni >> 1][(ni & 1) * 2 + 1]);
        }
        __syncthreads();

        // refill this stage (overlaps epilogue below)
        if (t + STAGES < TILES)
            copy_neg_tile(sb, tid, t % STAGES, negbase + (t + STAGES) * NT);
        CP_COMMIT();   // empty group at tail keeps wait_group accounting uniform

        // epilogue: online LSE in log2 domain (scores already log2-scaled)
        #pragma unroll
        for (int j = 0; j < 8; j++) {
            const int mi = j >> 1, hi = (j & 1) * 2;
            float x0 = C[mi][0][hi],     x1 = C[mi][0][hi + 1];
            float x2 = C[mi][1][hi],     x3 = C[mi][1][hi + 1];
            float x4 = C[mi][2][hi],     x5 = C[mi][2][hi + 1];
            float x6 = C[mi][3][hi],     x7 = C[mi][3][hi + 1];
            float tmax = fmaxf(fmaxf(fmaxf(x0, x1), fmaxf(x2, x3)),
                               fmaxf(fmaxf(x4, x5), fmaxf(x6, x7)));
            if (tmax > mrun[j]) {
                srun[j] *= ex2f(mrun[j] - tmax);
                mrun[j] = tmax;
            }
            const float mn = mrun[j];
            float acc = ex2f(x0 - mn) + ex2f(x1 - mn) + ex2f(x2 - mn) + ex2f(x3 - mn)
                      + ex2f(x4 - mn) + ex2f(x5 - mn) + ex2f(x6 - mn) + ex2f(x7 - mn);
            srun[j] += acc;
        }
    }

    // combine the 4 lanes that share each row (lane^1, lane^2)
    #pragma unroll
    for (int j = 0; j < 8; j++) {
        #pragma unroll
        for (int off = 1; off <= 2; off <<= 1) {
            float mo = __shfl_xor_sync(0xffffffffu, mrun[j], off);
            float so = __shfl_xor_sync(0xffffffffu, srun[j], off);
            float M = fmaxf(mrun[j], mo);
            srun[j] = srun[j] * ex2f(mrun[j] - M) + so * ex2f(mo - M);
            mrun[j] = M;
        }
    }

    __syncthreads();   // smem tiles no longer needed
    float* smm = reinterpret_cast<float*>(smem);          // [4][128]
    float* sms = smm + 512;
    if ((lane & 3) == 0) {
        #pragma unroll
        for (int j = 0; j < 8; j++) {
            int row = wm * 64 + (j >> 1) * 16 + (lane >> 2) + (j & 1) * 8;
            smm[wn * 128 + row] = mrun[j];
            sms[wn * 128 + row] = srun[j];
        }
    }
    __syncthreads();
    if (tid < 128) {
        float M = smm[tid];
        M = fmaxf(M, smm[128 + tid]);
        M = fmaxf(M, smm[256 + tid]);
        M = fmaxf(M, smm[384 + tid]);
        float S = sms[tid]       * ex2f(smm[tid]       - M)
                + sms[128 + tid] * ex2f(smm[128 + tid] - M)
                + sms[256 + tid] * ex2f(smm[256 + tid] - M)
                + sms[384 + tid] * ex2f(smm[384 + tid] - M);
        int grow = qbase + tid;
        g_pm[grow * SPLITS + blockIdx.y] = M;
        g_ps[grow * SPLITS + blockIdx.y] = S;
    }
}

// ============================================================================
// final reduction: combine splits, LSE, mean
// ============================================================================
__global__ void reduce_kernel(float* __restrict__ out) {
    __shared__ double sh[256];
    int tid = threadIdx.x;
    double acc = 0.0;
    for (int r = tid; r < NQ; r += 256) {
        float m0 = g_pm[2 * r], m1 = g_pm[2 * r + 1];
        float s0 = g_ps[2 * r], s1 = g_ps[2 * r + 1];
        float Mx = fmaxf(m0, m1);
        float S = s0 * ex2f(m0 - Mx) + s1 * ex2f(m1 - Mx);
        float lse = LN2F * (Mx + log2f(S));   // back to natural log
        acc += (double)(lse - g_poslogit[r]);
    }
    sh[tid] = acc;
    __syncthreads();
    for (int o = 128; o > 0; o >>= 1) {
        if (tid < o) sh[tid] += sh[tid + o];
        __syncthreads();
    }
    if (tid == 0) out[0] = (float)(sh[0] / (double)NQ);
}

// ============================================================================
// kernel_launch
// ============================================================================
extern "C" void kernel_launch(void* const* d_in, const int* in_sizes, int n_in,
                              void* d_out, int out_size) {
    (void)n_in; (void)out_size;
    const float* a0 = (const float*)d_in[0];
    const float* a1 = (const float*)d_in[1];
    const float* a2 = (const float*)d_in[2];
    const float *q, *p, *neg;
    if (in_sizes[2] == NNEG * KD)      { q = a0; p = a1; neg = a2; }
    else if (in_sizes[1] == NNEG * KD) { q = a0; p = a2; neg = a1; }
    else                               { q = a1; p = a2; neg = a0; }

    cudaFuncSetAttribute(conloss_main_kernel,
                         cudaFuncAttributeMaxDynamicSharedMemorySize, SMEM_TOTAL);

    prep_neg_kernel<<<(NNEG * KD) / 1024, 256>>>(neg);
    prep_q_kernel<<<NQ / 8, 256>>>(q, p);
    conloss_main_kernel<<<dim3(NQ / MB, SPLITS), 256, SMEM_TOTAL>>>();
    reduce_kernel<<<1, 256>>>((float*)d_out);
}

// round 3
// speedup vs baseline: 1.0642x; 1.0642x over previous
#include <cuda_runtime.h>
#include <cuda_fp16.h>
#include <cstdint>

// ============================================================================
// IWConLoss on GB300 (sm_103a via compute_103 baseline PTX):
//   scores = Q @ Neg^T / tau ; loss = mean( LSE_row(scores) - (Q.P)/tau )
// ldmatrix + mma.sync.m16n8k16 (fp16 in, fp32 acc), Q pre-scaled by log2(e)/tau.
// Epilogue phase-staggered across warp groups to overlap MUFU with tensor pipe.
// ============================================================================

static constexpr int NQ   = 8192;
static constexpr int NNEG = 16384;
static constexpr int KD   = 128;

static constexpr int MB = 128;     // query rows per CTA
static constexpr int NT = 128;     // negatives per tile
static constexpr int SPLITS = 2;   // neg splits -> grid 64 x 2 = 128 CTAs
static constexpr int TILES = NNEG / SPLITS / NT;   // 64
static constexpr int STAGES = 4;

static constexpr int PITCH = 272;                    // bytes per row: 128 fp16 + 8 pad
static constexpr int TILE_BYTES = 128 * PITCH;       // 34816
static constexpr int SMEM_TOTAL = TILE_BYTES * (1 + STAGES);  // 174080

static constexpr float INV_TAU = 5.0f;
static constexpr float C_T  = 7.2134752044448170f;   // log2(e)/tau
static constexpr float LN2F = 0.69314718055994531f;

static constexpr int RBLK = 32;                      // reduction blocks

// ---------------- device scratch ----------------
__device__ __align__(16) __half g_qh[NQ * KD];
__device__ __align__(16) __half g_nh[NNEG * KD];
__device__ float g_poslogit[NQ];
__device__ float g_pm[NQ * SPLITS];
__device__ float g_ps[NQ * SPLITS];
__device__ double g_part[RBLK];

// ---------------- helpers ----------------
__device__ __forceinline__ uint32_t smem_u32(const void* p) {
    uint32_t a;
    asm("{ .reg .u64 t; cvta.to.shared.u64 t, %1; cvt.u32.u64 %0, t; }"
        : "=r"(a) : "l"(p));
    return a;
}
__device__ __forceinline__ float ex2f(float x) {
    float r; asm("ex2.approx.ftz.f32 %0, %1;" : "=f"(r) : "f"(x)); return r;
}
__device__ __forceinline__ void cpa16(uint32_t dst, const void* src) {
    asm volatile("cp.async.cg.shared.global [%0], [%1], 16;" :: "r"(dst), "l"(src));
}
#define CP_COMMIT() asm volatile("cp.async.commit_group;" ::: "memory")
#define CP_WAIT(n)  asm volatile("cp.async.wait_group %0;" :: "n"(n) : "memory")

__device__ __forceinline__ void ldsm4(uint32_t& r0, uint32_t& r1, uint32_t& r2,
                                      uint32_t& r3, uint32_t addr) {
    asm volatile("ldmatrix.sync.aligned.m8n8.x4.shared.b16 {%0,%1,%2,%3}, [%4];"
        : "=r"(r0), "=r"(r1), "=r"(r2), "=r"(r3) : "r"(addr));
}
__device__ __forceinline__ void mma16816(float* d, const uint32_t* a,
                                         const uint32_t b0, const uint32_t b1) {
    asm volatile(
        "mma.sync.aligned.m16n8k16.row.col.f32.f16.f16.f32 "
        "{%0,%1,%2,%3}, {%4,%5,%6,%7}, {%8,%9}, {%0,%1,%2,%3};"
        : "+f"(d[0]), "+f"(d[1]), "+f"(d[2]), "+f"(d[3])
        : "r"(a[0]), "r"(a[1]), "r"(a[2]), "r"(a[3]), "r"(b0), "r"(b1));
}

// ============================================================================
// prep kernels
// ============================================================================
__global__ void prep_neg_kernel(const float* __restrict__ neg) {
    int i = (blockIdx.x * 256 + threadIdx.x) * 4;
    float4 v = *reinterpret_cast<const float4*>(neg + i);
    __half2* o = reinterpret_cast<__half2*>(g_nh + i);
    o[0] = __floats2half2_rn(v.x, v.y);
    o[1] = __floats2half2_rn(v.z, v.w);
}

__global__ void prep_q_kernel(const float* __restrict__ q, const float* __restrict__ pos) {
    int w = threadIdx.x >> 5, lane = threadIdx.x & 31;
    int row = blockIdx.x * 8 + w;
    const float4 q4 = *reinterpret_cast<const float4*>(q + row * KD + lane * 4);
    const float4 p4 = *reinterpret_cast<const float4*>(pos + row * KD + lane * 4);
    float d = q4.x * p4.x + q4.y * p4.y + q4.z * p4.z + q4.w * p4.w;
    #pragma unroll
    for (int o = 16; o > 0; o >>= 1) d += __shfl_xor_sync(0xffffffffu, d, o);
    if (lane == 0) g_poslogit[row] = d * INV_TAU;

    __half2* o = reinterpret_cast<__half2*>(g_qh + row * KD + lane * 4);
    o[0] = __floats2half2_rn(q4.x * C_T, q4.y * C_T);
    o[1] = __floats2half2_rn(q4.z * C_T, q4.w * C_T);
}

// ============================================================================
// main fused kernel
// ============================================================================
__device__ __forceinline__ void copy_q_block(uint32_t sb, int tid, int qbase) {
    #pragma unroll
    for (int j = 0; j < 8; j++) {
        int idx = j * 256 + tid;
        int row = idx >> 4, c = idx & 15;
        cpa16(sb + (uint32_t)(row * PITCH + c * 16), g_qh + (qbase + row) * KD + c * 8);
    }
}
__device__ __forceinline__ void copy_neg_tile(uint32_t sb, int tid, int stage, int rowbase) {
    uint32_t base = sb + (uint32_t)(TILE_BYTES * (1 + stage));
    #pragma unroll
    for (int j = 0; j < 8; j++) {
        int idx = j * 256 + tid;
        int row = idx >> 4, c = idx & 15;
        cpa16(base + (uint32_t)(row * PITCH + c * 16),
              g_nh + (rowbase + row) * KD + c * 8);
    }
}

// online LSE update over one warp-tile's worth of scores held in C
__device__ __forceinline__ void epilogue(const float C[4][4][4], float* mrun, float* srun) {
    #pragma unroll
    for (int j = 0; j < 8; j++) {
        const int mi = j >> 1, hi = (j & 1) * 2;
        float x0 = C[mi][0][hi],     x1 = C[mi][0][hi + 1];
        float x2 = C[mi][1][hi],     x3 = C[mi][1][hi + 1];
        float x4 = C[mi][2][hi],     x5 = C[mi][2][hi + 1];
        float x6 = C[mi][3][hi],     x7 = C[mi][3][hi + 1];
        float tmax = fmaxf(fmaxf(fmaxf(x0, x1), fmaxf(x2, x3)),
                           fmaxf(fmaxf(x4, x5), fmaxf(x6, x7)));
        if (tmax > mrun[j]) {
            srun[j] *= ex2f(mrun[j] - tmax);
            mrun[j] = tmax;
        }
        const float mn = mrun[j];
        srun[j] += ex2f(x0 - mn) + ex2f(x1 - mn) + ex2f(x2 - mn) + ex2f(x3 - mn)
                 + ex2f(x4 - mn) + ex2f(x5 - mn) + ex2f(x6 - mn) + ex2f(x7 - mn);
    }
}

__global__ __launch_bounds__(256, 1) void conloss_main_kernel() {
    extern __shared__ char smem[];
    uint32_t sb = smem_u32(smem);
    const int tid = threadIdx.x, warp = tid >> 5, lane = tid & 31;
    const int wm = warp & 1;          // 2 warp-rows of 64
    const int wn = warp >> 1;         // 4 warp-cols of 32
    // Phase group: warps 0-3 epilogue-FIRST (previous tile), warps 4-7 epilogue-AFTER.
    // SMSP = warp % 4, so each SMSP holds one warp of each group -> tensor and
    // MUFU pipes are both fed throughout the inter-barrier window.
    const bool epiFirst = (warp < 4);
    const int qbase = blockIdx.x * MB;
    const int negbase = blockIdx.y * (NNEG / SPLITS);

    copy_q_block(sb, tid, qbase);
    copy_neg_tile(sb, tid, 0, negbase);
    CP_COMMIT();
    #pragma unroll
    for (int s2 = 1; s2 < STAGES; s2++) {
        copy_neg_tile(sb, tid, s2, negbase + s2 * NT);
        CP_COMMIT();
    }

    const uint32_t aBase = sb + (uint32_t)((wm * 64 + (lane & 15)) * PITCH + ((lane >> 4) * 16));
    const uint32_t bOff = (uint32_t)(((wn * 32) + (lane & 7) + ((lane >> 4) << 3)) * PITCH
                                     + (((lane >> 3) & 1) * 16));

    float C[4][4][4];
    float mrun[8], srun[8];
    #pragma unroll
    for (int j = 0; j < 8; j++) { mrun[j] = -1e30f; srun[j] = 0.0f; }

    for (int t = 0; t < TILES; t++) {
        CP_WAIT(STAGES - 1);
        __syncthreads();

        if (epiFirst && t > 0) epilogue(C, mrun, srun);   // previous tile's scores

        #pragma unroll
        for (int mi = 0; mi < 4; mi++)
            #pragma unroll
            for (int ni = 0; ni < 4; ni++)
                #pragma unroll
                for (int r = 0; r < 4; r++) C[mi][ni][r] = 0.0f;

        const uint32_t bBase = sb + (uint32_t)(TILE_BYTES * (1 + (t % STAGES))) + bOff;

        #pragma unroll
        for (int ks = 0; ks < 8; ks++) {
            uint32_t A[4][4], B[2][4];
            #pragma unroll
            for (int mi = 0; mi < 4; mi++)
                ldsm4(A[mi][0], A[mi][1], A[mi][2], A[mi][3],
                      aBase + (uint32_t)(mi * 16 * PITCH + ks * 32));
            #pragma unroll
            for (int np = 0; np < 2; np++)
                ldsm4(B[np][0], B[np][1], B[np][2], B[np][3],
                      bBase + (uint32_t)(np * 16 * PITCH + ks * 32));
            #pragma unroll
            for (int mi = 0; mi < 4; mi++)
                #pragma unroll
                for (int ni = 0; ni < 4; ni++)
                    mma16816(C[mi][ni], A[mi],
                             B[ni >> 1][(ni & 1) * 2], B[ni >> 1][(ni & 1) * 2 + 1]);
        }
        __syncthreads();

        if (t + STAGES < TILES)
            copy_neg_tile(sb, tid, t % STAGES, negbase + (t + STAGES) * NT);
        CP_COMMIT();

        if (!epiFirst) epilogue(C, mrun, srun);
    }
    if (epiFirst) epilogue(C, mrun, srun);   // tail: last tile for early group

    // combine the 4 lanes sharing each row
    #pragma unroll
    for (int j = 0; j < 8; j++) {
        #pragma unroll
        for (int off = 1; off <= 2; off <<= 1) {
            float mo = __shfl_xor_sync(0xffffffffu, mrun[j], off);
            float so = __shfl_xor_sync(0xffffffffu, srun[j], off);
            float M = fmaxf(mrun[j], mo);
            srun[j] = srun[j] * ex2f(mrun[j] - M) + so * ex2f(mo - M);
            mrun[j] = M;
        }
    }

    __syncthreads();
    float* smm = reinterpret_cast<float*>(smem);          // [4][128]
    float* sms = smm + 512;
    if ((lane & 3) == 0) {
        #pragma unroll
        for (int j = 0; j < 8; j++) {
            int row = wm * 64 + (j >> 1) * 16 + (lane >> 2) + (j & 1) * 8;
            smm[wn * 128 + row] = mrun[j];
            sms[wn * 128 + row] = srun[j];
        }
    }
    __syncthreads();
    if (tid < 128) {
        float M = fmaxf(fmaxf(smm[tid], smm[128 + tid]),
                        fmaxf(smm[256 + tid], smm[384 + tid]));
        float S = sms[tid]       * ex2f(smm[tid]       - M)
                + sms[128 + tid] * ex2f(smm[128 + tid] - M)
                + sms[256 + tid] * ex2f(smm[256 + tid] - M)
                + sms[384 + tid] * ex2f(smm[384 + tid] - M);
        int grow = qbase + tid;
        g_pm[grow * SPLITS + blockIdx.y] = M;
        g_ps[grow * SPLITS + blockIdx.y] = S;
    }
}

// ============================================================================
// reduction: 32-block partial (deterministic), then tiny final combine
// ============================================================================
__global__ void reduce_partial_kernel() {
    __shared__ double sh[256];
    int tid = threadIdx.x;
    int base = blockIdx.x * (NQ / RBLK);          // 256 rows per block
    int r = base + tid;
    float m0 = g_pm[2 * r], m1 = g_pm[2 * r + 1];
    float s0 = g_ps[2 * r], s1 = g_ps[2 * r + 1];
    float Mx = fmaxf(m0, m1);
    float S = s0 * ex2f(m0 - Mx) + s1 * ex2f(m1 - Mx);
    float lse = LN2F * (Mx + log2f(S));
    sh[tid] = (double)(lse - g_poslogit[r]);
    __syncthreads();
    for (int o = 128; o > 0; o >>= 1) {
        if (tid < o) sh[tid] += sh[tid + o];
        __syncthreads();
    }
    if (tid == 0) g_part[blockIdx.x] = sh[0];
}

__global__ void reduce_final_kernel(float* __restrict__ out) {
    if (threadIdx.x == 0) {
        double acc = 0.0;
        #pragma unroll
        for (int i = 0; i < RBLK; i++) acc += g_part[i];
        out[0] = (float)(acc / (double)NQ);
    }
}

// ============================================================================
// kernel_launch
// ============================================================================
extern "C" void kernel_launch(void* const* d_in, const int* in_sizes, int n_in,
                              void* d_out, int out_size) {
    (void)n_in; (void)out_size;
    const float* a0 = (const float*)d_in[0];
    const float* a1 = (const float*)d_in[1];
    const float* a2 = (const float*)d_in[2];
    const float *q, *p, *neg;
    if (in_sizes[2] == NNEG * KD)      { q = a0; p = a1; neg = a2; }
    else if (in_sizes[1] == NNEG * KD) { q = a0; p = a2; neg = a1; }
    else                               { q = a1; p = a2; neg = a0; }

    cudaFuncSetAttribute(conloss_main_kernel,
                         cudaFuncAttributeMaxDynamicSharedMemorySize, SMEM_TOTAL);

    prep_neg_kernel<<<(NNEG * KD) / 1024, 256>>>(neg);
    prep_q_kernel<<<NQ / 8, 256>>>(q, p);
    conloss_main_kernel<<<dim3(NQ / MB, SPLITS), 256, SMEM_TOTAL>>>();
    reduce_partial_kernel<<<RBLK, 256>>>();
    reduce_final_kernel<<<1, 32>>>((float*)d_out);
}

// round 4
// speedup vs baseline: 1.1944x; 1.1223x over previous
#include <cuda_runtime.h>
#include <cuda_fp16.h>
#include <cstdint>

// ============================================================================
// IWConLoss on GB300 (sm_103a via compute_103 baseline PTX):
//   scores = Q @ Neg^T / tau ; loss = mean( LSE_row(scores) - (Q.P)/tau )
// ldmatrix + mma.sync.m16n8k16 (fp16 in, fp32 acc), Q pre-scaled by log2(e)/tau.
// R3: occupancy-2 (2 CTAs/SM) + 512-CTA grid to cover all 148 SMs and keep the
// HMMA pipe saturated across barrier/epilogue windows.
// ============================================================================

static constexpr int NQ   = 8192;
static constexpr int NNEG = 16384;
static constexpr int KD   = 128;

static constexpr int MB = 128;     // query rows per CTA
static constexpr int NT = 128;     // negatives per tile
static constexpr int SPLITS = 8;   // neg splits -> grid 64 x 8 = 512 CTAs
static constexpr int TILES = NNEG / SPLITS / NT;   // 16
static constexpr int STAGES = 2;

static constexpr int PITCH = 272;                    // bytes per row: 128 fp16 + 8 pad
static constexpr int TILE_BYTES = 128 * PITCH;       // 34816
static constexpr int SMEM_TOTAL = TILE_BYTES * (1 + STAGES);  // 104448 -> 2 CTAs/SM

static constexpr float INV_TAU = 5.0f;
static constexpr float C_T  = 7.2134752044448170f;   // log2(e)/tau
static constexpr float LN2F = 0.69314718055994531f;

static constexpr int RBLK = 32;                      // reduction blocks

// ---------------- device scratch ----------------
__device__ __align__(16) __half g_qh[NQ * KD];
__device__ __align__(16) __half g_nh[NNEG * KD];
__device__ float g_poslogit[NQ];
__device__ float g_pm[NQ * SPLITS];
__device__ float g_ps[NQ * SPLITS];
__device__ double g_part[RBLK];

// ---------------- helpers ----------------
__device__ __forceinline__ uint32_t smem_u32(const void* p) {
    uint32_t a;
    asm("{ .reg .u64 t; cvta.to.shared.u64 t, %1; cvt.u32.u64 %0, t; }"
        : "=r"(a) : "l"(p));
    return a;
}
__device__ __forceinline__ float ex2f(float x) {
    float r; asm("ex2.approx.ftz.f32 %0, %1;" : "=f"(r) : "f"(x)); return r;
}
__device__ __forceinline__ void cpa16(uint32_t dst, const void* src) {
    asm volatile("cp.async.cg.shared.global [%0], [%1], 16;" :: "r"(dst), "l"(src));
}
#define CP_COMMIT() asm volatile("cp.async.commit_group;" ::: "memory")
#define CP_WAIT(n)  asm volatile("cp.async.wait_group %0;" :: "n"(n) : "memory")

__device__ __forceinline__ void ldsm4(uint32_t& r0, uint32_t& r1, uint32_t& r2,
                                      uint32_t& r3, uint32_t addr) {
    asm volatile("ldmatrix.sync.aligned.m8n8.x4.shared.b16 {%0,%1,%2,%3}, [%4];"
        : "=r"(r0), "=r"(r1), "=r"(r2), "=r"(r3) : "r"(addr));
}
__device__ __forceinline__ void mma16816(float* d, const uint32_t* a,
                                         const uint32_t b0, const uint32_t b1) {
    asm volatile(
        "mma.sync.aligned.m16n8k16.row.col.f32.f16.f16.f32 "
        "{%0,%1,%2,%3}, {%4,%5,%6,%7}, {%8,%9}, {%0,%1,%2,%3};"
        : "+f"(d[0]), "+f"(d[1]), "+f"(d[2]), "+f"(d[3])
        : "r"(a[0]), "r"(a[1]), "r"(a[2]), "r"(a[3]), "r"(b0), "r"(b1));
}

// ============================================================================
// prep kernels
// ============================================================================
__global__ void prep_neg_kernel(const float* __restrict__ neg) {
    int i = (blockIdx.x * 256 + threadIdx.x) * 4;
    float4 v = *reinterpret_cast<const float4*>(neg + i);
    __half2* o = reinterpret_cast<__half2*>(g_nh + i);
    o[0] = __floats2half2_rn(v.x, v.y);
    o[1] = __floats2half2_rn(v.z, v.w);
}

__global__ void prep_q_kernel(const float* __restrict__ q, const float* __restrict__ pos) {
    int w = threadIdx.x >> 5, lane = threadIdx.x & 31;
    int row = blockIdx.x * 8 + w;
    const float4 q4 = *reinterpret_cast<const float4*>(q + row * KD + lane * 4);
    const float4 p4 = *reinterpret_cast<const float4*>(pos + row * KD + lane * 4);
    float d = q4.x * p4.x + q4.y * p4.y + q4.z * p4.z + q4.w * p4.w;
    #pragma unroll
    for (int o = 16; o > 0; o >>= 1) d += __shfl_xor_sync(0xffffffffu, d, o);
    if (lane == 0) g_poslogit[row] = d * INV_TAU;

    __half2* o = reinterpret_cast<__half2*>(g_qh + row * KD + lane * 4);
    o[0] = __floats2half2_rn(q4.x * C_T, q4.y * C_T);
    o[1] = __floats2half2_rn(q4.z * C_T, q4.w * C_T);
}

// ============================================================================
// main fused kernel
// ============================================================================
__device__ __forceinline__ void copy_q_block(uint32_t sb, int tid, int qbase) {
    #pragma unroll
    for (int j = 0; j < 8; j++) {
        int idx = j * 256 + tid;
        int row = idx >> 4, c = idx & 15;
        cpa16(sb + (uint32_t)(row * PITCH + c * 16), g_qh + (qbase + row) * KD + c * 8);
    }
}
__device__ __forceinline__ void copy_neg_tile(uint32_t sb, int tid, int stage, int rowbase) {
    uint32_t base = sb + (uint32_t)(TILE_BYTES * (1 + stage));
    #pragma unroll
    for (int j = 0; j < 8; j++) {
        int idx = j * 256 + tid;
        int row = idx >> 4, c = idx & 15;
        cpa16(base + (uint32_t)(row * PITCH + c * 16),
              g_nh + (rowbase + row) * KD + c * 8);
    }
}

// online LSE update over one warp-tile's worth of scores held in C
__device__ __forceinline__ void epilogue(const float C[4][4][4], float* mrun, float* srun) {
    #pragma unroll
    for (int j = 0; j < 8; j++) {
        const int mi = j >> 1, hi = (j & 1) * 2;
        float x0 = C[mi][0][hi],     x1 = C[mi][0][hi + 1];
        float x2 = C[mi][1][hi],     x3 = C[mi][1][hi + 1];
        float x4 = C[mi][2][hi],     x5 = C[mi][2][hi + 1];
        float x6 = C[mi][3][hi],     x7 = C[mi][3][hi + 1];
        float tmax = fmaxf(fmaxf(fmaxf(x0, x1), fmaxf(x2, x3)),
                           fmaxf(fmaxf(x4, x5), fmaxf(x6, x7)));
        if (tmax > mrun[j]) {
            srun[j] *= ex2f(mrun[j] - tmax);
            mrun[j] = tmax;
        }
        const float mn = mrun[j];
        srun[j] += ex2f(x0 - mn) + ex2f(x1 - mn) + ex2f(x2 - mn) + ex2f(x3 - mn)
                 + ex2f(x4 - mn) + ex2f(x5 - mn) + ex2f(x6 - mn) + ex2f(x7 - mn);
    }
}

__global__ __launch_bounds__(256, 2) void conloss_main_kernel() {
    extern __shared__ char smem[];
    uint32_t sb = smem_u32(smem);
    const int tid = threadIdx.x, warp = tid >> 5, lane = tid & 31;
    const int wm = warp & 1;          // 2 warp-rows of 64
    const int wn = warp >> 1;         // 4 warp-cols of 32
    const bool epiFirst = (warp < 4); // phase-staggered epilogue across SMSP pairs
    const int qbase = blockIdx.x * MB;
    const int negbase = blockIdx.y * (NNEG / SPLITS);

    copy_q_block(sb, tid, qbase);
    copy_neg_tile(sb, tid, 0, negbase);
    CP_COMMIT();
    copy_neg_tile(sb, tid, 1, negbase + NT);
    CP_COMMIT();

    const uint32_t aBase = sb + (uint32_t)((wm * 64 + (lane & 15)) * PITCH + ((lane >> 4) * 16));
    const uint32_t bOff = (uint32_t)(((wn * 32) + (lane & 7) + ((lane >> 4) << 3)) * PITCH
                                     + (((lane >> 3) & 1) * 16));

    float C[4][4][4];
    float mrun[8], srun[8];
    #pragma unroll
    for (int j = 0; j < 8; j++) { mrun[j] = -1e30f; srun[j] = 0.0f; }

    for (int t = 0; t < TILES; t++) {
        CP_WAIT(STAGES - 1);
        __syncthreads();

        if (epiFirst && t > 0) epilogue(C, mrun, srun);   // previous tile's scores

        #pragma unroll
        for (int mi = 0; mi < 4; mi++)
            #pragma unroll
            for (int ni = 0; ni < 4; ni++)
                #pragma unroll
                for (int r = 0; r < 4; r++) C[mi][ni][r] = 0.0f;

        const uint32_t bBase = sb + (uint32_t)(TILE_BYTES * (1 + (t % STAGES))) + bOff;

        #pragma unroll
        for (int ks = 0; ks < 8; ks++) {
            uint32_t A[4][4], B[2][4];
            #pragma unroll
            for (int mi = 0; mi < 4; mi++)
                ldsm4(A[mi][0], A[mi][1], A[mi][2], A[mi][3],
                      aBase + (uint32_t)(mi * 16 * PITCH + ks * 32));
            #pragma unroll
            for (int np = 0; np < 2; np++)
                ldsm4(B[np][0], B[np][1], B[np][2], B[np][3],
                      bBase + (uint32_t)(np * 16 * PITCH + ks * 32));
            #pragma unroll
            for (int mi = 0; mi < 4; mi++)
                #pragma unroll
                for (int ni = 0; ni < 4; ni++)
                    mma16816(C[mi][ni], A[mi],
                             B[ni >> 1][(ni & 1) * 2], B[ni >> 1][(ni & 1) * 2 + 1]);
        }
        __syncthreads();

        if (t + STAGES < TILES)
            copy_neg_tile(sb, tid, t % STAGES, negbase + (t + STAGES) * NT);
        CP_COMMIT();

        if (!epiFirst) epilogue(C, mrun, srun);
    }
    if (epiFirst) epilogue(C, mrun, srun);   // tail: last tile for early group

    // combine the 4 lanes sharing each row
    #pragma unroll
    for (int j = 0; j < 8; j++) {
        #pragma unroll
        for (int off = 1; off <= 2; off <<= 1) {
            float mo = __shfl_xor_sync(0xffffffffu, mrun[j], off);
            float so = __shfl_xor_sync(0xffffffffu, srun[j], off);
            float M = fmaxf(mrun[j], mo);
            srun[j] = srun[j] * ex2f(mrun[j] - M) + so * ex2f(mo - M);
            mrun[j] = M;
        }
    }

    __syncthreads();
    float* smm = reinterpret_cast<float*>(smem);          // [4][128]
    float* sms = smm + 512;
    if ((lane & 3) == 0) {
        #pragma unroll
        for (int j = 0; j < 8; j++) {
            int row = wm * 64 + (j >> 1) * 16 + (lane >> 2) + (j & 1) * 8;
            smm[wn * 128 + row] = mrun[j];
            sms[wn * 128 + row] = srun[j];
        }
    }
    __syncthreads();
    if (tid < 128) {
        float M = fmaxf(fmaxf(smm[tid], smm[128 + tid]),
                        fmaxf(smm[256 + tid], smm[384 + tid]));
        float S = sms[tid]       * ex2f(smm[tid]       - M)
                + sms[128 + tid] * ex2f(smm[128 + tid] - M)
                + sms[256 + tid] * ex2f(smm[256 + tid] - M)
                + sms[384 + tid] * ex2f(smm[384 + tid] - M);
        int grow = qbase + tid;
        g_pm[grow * SPLITS + blockIdx.y] = M;
        g_ps[grow * SPLITS + blockIdx.y] = S;
    }
}

// ============================================================================
// reduction: 32-block partial (deterministic), then tiny final combine
// ============================================================================
__global__ void reduce_partial_kernel() {
    __shared__ double sh[256];
    int tid = threadIdx.x;
    int r = blockIdx.x * (NQ / RBLK) + tid;       // 256 rows per block
    float M = g_pm[r * SPLITS];
    #pragma unroll
    for (int j = 1; j < SPLITS; j++) M = fmaxf(M, g_pm[r * SPLITS + j]);
    float S = 0.0f;
    #pragma unroll
    for (int j = 0; j < SPLITS; j++)
        S += g_ps[r * SPLITS + j] * ex2f(g_pm[r * SPLITS + j] - M);
    float lse = LN2F * (M + log2f(S));
    sh[tid] = (double)(lse - g_poslogit[r]);
    __syncthreads();
    for (int o = 128; o > 0; o >>= 1) {
        if (tid < o) sh[tid] += sh[tid + o];
        __syncthreads();
    }
    if (tid == 0) g_part[blockIdx.x] = sh[0];
}

__global__ void reduce_final_kernel(float* __restrict__ out) {
    if (threadIdx.x == 0) {
        double acc = 0.0;
        #pragma unroll
        for (int i = 0; i < RBLK; i++) acc += g_part[i];
        out[0] = (float)(acc / (double)NQ);
    }
}

// ============================================================================
// kernel_launch
// ============================================================================
extern "C" void kernel_launch(void* const* d_in, const int* in_sizes, int n_in,
                              void* d_out, int out_size) {
    (void)n_in; (void)out_size;
    const float* a0 = (const float*)d_in[0];
    const float* a1 = (const float*)d_in[1];
    const float* a2 = (const float*)d_in[2];
    const float *q, *p, *neg;
    if (in_sizes[2] == NNEG * KD)      { q = a0; p = a1; neg = a2; }
    else if (in_sizes[1] == NNEG * KD) { q = a0; p = a2; neg = a1; }
    else                               { q = a1; p = a2; neg = a0; }

    cudaFuncSetAttribute(conloss_main_kernel,
                         cudaFuncAttributeMaxDynamicSharedMemorySize, SMEM_TOTAL);

    prep_neg_kernel<<<(NNEG * KD) / 1024, 256>>>(neg);
    prep_q_kernel<<<NQ / 8, 256>>>(q, p);
    conloss_main_kernel<<<dim3(NQ / MB, SPLITS), 256, SMEM_TOTAL>>>();
    reduce_partial_kernel<<<RBLK, 256>>>();
    reduce_final_kernel<<<1, 32>>>((float*)d_out);
}

// round 5
// speedup vs baseline: 1.3342x; 1.1171x over previous
#include <cuda_runtime.h>
#include <cuda_fp16.h>
#include <cstdint>

// ============================================================================
// IWConLoss on GB300 (sm_103a via compute_103 baseline PTX):
//   scores = Q @ Neg^T / tau ; loss = mean( LSE_row(scores) - (Q.P)/tau )
// R4: 32x32 warp tiles (C=32 regs), NT=64, 3 CTAs/SM (6 warps/SMSP) to fix the
// issue/latency bound seen at occ-2 (IPC 0.26).
// ============================================================================

static constexpr int NQ   = 8192;
static constexpr int NNEG = 16384;
static constexpr int KD   = 128;

static constexpr int MB = 128;      // query rows per CTA
static constexpr int NT = 64;       // negatives per tile
static constexpr int SPLITS = 16;   // grid = 64 x 16 = 1024 CTAs
static constexpr int TILES = NNEG / SPLITS / NT;   // 16
static constexpr int STAGES = 2;

static constexpr int PITCH = 272;                   // 128 fp16 + 8 pad
static constexpr int QT_BYTES = 128 * PITCH;        // 34816
static constexpr int NT_BYTES = NT * PITCH;         // 17408
static constexpr int SMEM_TOTAL = QT_BYTES + STAGES * NT_BYTES;  // 69632 -> 3 CTAs/SM

static constexpr float INV_TAU = 5.0f;
static constexpr float C_T  = 7.2134752044448170f;  // log2(e)/tau
static constexpr float LN2F = 0.69314718055994531f;

// ---------------- device scratch ----------------
__device__ __align__(16) __half g_qh[NQ * KD];
__device__ __align__(16) __half g_nh[NNEG * KD];
__device__ float g_poslogit[NQ];
__device__ float g_pm[NQ * SPLITS];
__device__ float g_ps[NQ * SPLITS];
__device__ double g_part[64];

// ---------------- helpers ----------------
__device__ __forceinline__ uint32_t smem_u32(const void* p) {
    uint32_t a;
    asm("{ .reg .u64 t; cvta.to.shared.u64 t, %1; cvt.u32.u64 %0, t; }"
        : "=r"(a) : "l"(p));
    return a;
}
__device__ __forceinline__ float ex2f(float x) {
    float r; asm("ex2.approx.ftz.f32 %0, %1;" : "=f"(r) : "f"(x)); return r;
}
__device__ __forceinline__ void cpa16(uint32_t dst, const void* src) {
    asm volatile("cp.async.cg.shared.global [%0], [%1], 16;" :: "r"(dst), "l"(src));
}
#define CP_COMMIT() asm volatile("cp.async.commit_group;" ::: "memory")
#define CP_WAIT(n)  asm volatile("cp.async.wait_group %0;" :: "n"(n) : "memory")

__device__ __forceinline__ void ldsm4(uint32_t& r0, uint32_t& r1, uint32_t& r2,
                                      uint32_t& r3, uint32_t addr) {
    asm volatile("ldmatrix.sync.aligned.m8n8.x4.shared.b16 {%0,%1,%2,%3}, [%4];"
        : "=r"(r0), "=r"(r1), "=r"(r2), "=r"(r3) : "r"(addr));
}
__device__ __forceinline__ void mma16816(float* d, const uint32_t* a,
                                         const uint32_t b0, const uint32_t b1) {
    asm volatile(
        "mma.sync.aligned.m16n8k16.row.col.f32.f16.f16.f32 "
        "{%0,%1,%2,%3}, {%4,%5,%6,%7}, {%8,%9}, {%0,%1,%2,%3};"
        : "+f"(d[0]), "+f"(d[1]), "+f"(d[2]), "+f"(d[3])
        : "r"(a[0]), "r"(a[1]), "r"(a[2]), "r"(a[3]), "r"(b0), "r"(b1));
}

// ============================================================================
// prep kernels
// ============================================================================
__global__ void prep_neg_kernel(const float* __restrict__ neg) {
    int i = (blockIdx.x * 256 + threadIdx.x) * 4;
    float4 v = *reinterpret_cast<const float4*>(neg + i);
    __half2* o = reinterpret_cast<__half2*>(g_nh + i);
    o[0] = __floats2half2_rn(v.x, v.y);
    o[1] = __floats2half2_rn(v.z, v.w);
}

__global__ void prep_q_kernel(const float* __restrict__ q, const float* __restrict__ pos) {
    int w = threadIdx.x >> 5, lane = threadIdx.x & 31;
    int row = blockIdx.x * 8 + w;
    const float4 q4 = *reinterpret_cast<const float4*>(q + row * KD + lane * 4);
    const float4 p4 = *reinterpret_cast<const float4*>(pos + row * KD + lane * 4);
    float d = q4.x * p4.x + q4.y * p4.y + q4.z * p4.z + q4.w * p4.w;
    #pragma unroll
    for (int o = 16; o > 0; o >>= 1) d += __shfl_xor_sync(0xffffffffu, d, o);
    if (lane == 0) g_poslogit[row] = d * INV_TAU;

    __half2* o = reinterpret_cast<__half2*>(g_qh + row * KD + lane * 4);
    o[0] = __floats2half2_rn(q4.x * C_T, q4.y * C_T);
    o[1] = __floats2half2_rn(q4.z * C_T, q4.w * C_T);
}

// ============================================================================
// main fused kernel
// ============================================================================
__device__ __forceinline__ void copy_q_block(uint32_t sb, int tid, int qbase) {
    #pragma unroll
    for (int j = 0; j < 8; j++) {
        int idx = j * 256 + tid;
        int row = idx >> 4, c = idx & 15;
        cpa16(sb + (uint32_t)(row * PITCH + c * 16), g_qh + (qbase + row) * KD + c * 8);
    }
}
__device__ __forceinline__ void copy_neg_tile(uint32_t sb, int tid, int stage, int rowbase) {
    uint32_t base = sb + (uint32_t)(QT_BYTES + NT_BYTES * stage);
    #pragma unroll
    for (int j = 0; j < 4; j++) {
        int idx = j * 256 + tid;                 // 0..1023
        int row = idx >> 4, c = idx & 15;
        cpa16(base + (uint32_t)(row * PITCH + c * 16),
              g_nh + (rowbase + row) * KD + c * 8);
    }
}

// online LSE over one 32x32 warp tile: 4 row-slots x 8 elements
__device__ __forceinline__ void epilogue(const float C[2][4][4], float* mrun, float* srun) {
    #pragma unroll
    for (int j = 0; j < 4; j++) {
        const int mi = j >> 1, hi = (j & 1) * 2;
        float x0 = C[mi][0][hi],     x1 = C[mi][0][hi + 1];
        float x2 = C[mi][1][hi],     x3 = C[mi][1][hi + 1];
        float x4 = C[mi][2][hi],     x5 = C[mi][2][hi + 1];
        float x6 = C[mi][3][hi],     x7 = C[mi][3][hi + 1];
        float tmax = fmaxf(fmaxf(fmaxf(x0, x1), fmaxf(x2, x3)),
                           fmaxf(fmaxf(x4, x5), fmaxf(x6, x7)));
        if (tmax > mrun[j]) {
            srun[j] *= ex2f(mrun[j] - tmax);
            mrun[j] = tmax;
        }
        const float mn = mrun[j];
        srun[j] += ex2f(x0 - mn) + ex2f(x1 - mn) + ex2f(x2 - mn) + ex2f(x3 - mn)
                 + ex2f(x4 - mn) + ex2f(x5 - mn) + ex2f(x6 - mn) + ex2f(x7 - mn);
    }
}

__global__ __launch_bounds__(256, 3) void conloss_main_kernel() {
    extern __shared__ char smem[];
    uint32_t sb = smem_u32(smem);
    const int tid = threadIdx.x, warp = tid >> 5, lane = tid & 31;
    const int wm = warp & 3;          // 4 warp-rows of 32
    const int wn = warp >> 2;         // 2 warp-cols of 32
    const bool epiFirst = (warp < 4); // one warp of each phase per SMSP
    const int qbase = blockIdx.x * MB;
    const int negbase = blockIdx.y * (NNEG / SPLITS);

    copy_q_block(sb, tid, qbase);
    copy_neg_tile(sb, tid, 0, negbase);
    CP_COMMIT();
    copy_neg_tile(sb, tid, 1, negbase + NT);
    CP_COMMIT();

    // A (Q): rows wm*32 + mi*16 + (lane&15); k-byte = (lane>>4)*16 (+ks*32)
    const uint32_t aBase = sb + (uint32_t)((wm * 32 + (lane & 15)) * PITCH + ((lane >> 4) * 16));
    // B (Neg): cols wn*32 + np*16 + (lane&7)+(lane>>4)*8 ; k-byte = ((lane>>3)&1)*16
    const uint32_t bOff = (uint32_t)(((wn * 32) + (lane & 7) + ((lane >> 4) << 3)) * PITCH
                                     + (((lane >> 3) & 1) * 16));

    float C[2][4][4];
    float mrun[4], srun[4];
    #pragma unroll
    for (int j = 0; j < 4; j++) { mrun[j] = -1e30f; srun[j] = 0.0f; }

    for (int t = 0; t < TILES; t++) {
        CP_WAIT(STAGES - 1);
        __syncthreads();

        if (epiFirst && t > 0) epilogue(C, mrun, srun);

        #pragma unroll
        for (int mi = 0; mi < 2; mi++)
            #pragma unroll
            for (int ni = 0; ni < 4; ni++)
                #pragma unroll
                for (int r = 0; r < 4; r++) C[mi][ni][r] = 0.0f;

        const uint32_t bBase = sb + (uint32_t)(QT_BYTES + NT_BYTES * (t & 1)) + bOff;

        #pragma unroll
        for (int ks = 0; ks < 8; ks++) {
            uint32_t A[2][4], B[2][4];
            #pragma unroll
            for (int mi = 0; mi < 2; mi++)
                ldsm4(A[mi][0], A[mi][1], A[mi][2], A[mi][3],
                      aBase + (uint32_t)(mi * 16 * PITCH + ks * 32));
            #pragma unroll
            for (int np = 0; np < 2; np++)
                ldsm4(B[np][0], B[np][1], B[np][2], B[np][3],
                      bBase + (uint32_t)(np * 16 * PITCH + ks * 32));
            #pragma unroll
            for (int mi = 0; mi < 2; mi++)
                #pragma unroll
                for (int ni = 0; ni < 4; ni++)
                    mma16816(C[mi][ni], A[mi],
                             B[ni >> 1][(ni & 1) * 2], B[ni >> 1][(ni & 1) * 2 + 1]);
        }
        __syncthreads();

        if (t + STAGES < TILES)
            copy_neg_tile(sb, tid, t & 1, negbase + (t + STAGES) * NT);
        CP_COMMIT();

        if (!epiFirst) epilogue(C, mrun, srun);
    }
    if (epiFirst) epilogue(C, mrun, srun);

    // combine the 4 lanes sharing each row
    #pragma unroll
    for (int j = 0; j < 4; j++) {
        #pragma unroll
        for (int off = 1; off <= 2; off <<= 1) {
            float mo = __shfl_xor_sync(0xffffffffu, mrun[j], off);
            float so = __shfl_xor_sync(0xffffffffu, srun[j], off);
            float M = fmaxf(mrun[j], mo);
            srun[j] = srun[j] * ex2f(mrun[j] - M) + so * ex2f(mo - M);
            mrun[j] = M;
        }
    }

    __syncthreads();
    float* smm = reinterpret_cast<float*>(smem);          // [2][128]
    float* sms = smm + 256;
    if ((lane & 3) == 0) {
        #pragma unroll
        for (int j = 0; j < 4; j++) {
            int row = wm * 32 + (j >> 1) * 16 + (j & 1) * 8 + (lane >> 2);
            smm[wn * 128 + row] = mrun[j];
            sms[wn * 128 + row] = srun[j];
        }
    }
    __syncthreads();
    if (tid < 128) {
        float m0 = smm[tid], m1 = smm[128 + tid];
        float M = fmaxf(m0, m1);
        float S = sms[tid] * ex2f(m0 - M) + sms[128 + tid] * ex2f(m1 - M);
        int grow = qbase + tid;
        g_pm[grow * SPLITS + blockIdx.y] = M;
        g_ps[grow * SPLITS + blockIdx.y] = S;
    }
}

// ============================================================================
// reduction: 64-block partial (1 row/thread), tiny final combine
// ============================================================================
__global__ void reduce_partial_kernel() {
    __shared__ double sh[128];
    int tid = threadIdx.x;
    int r = blockIdx.x * 128 + tid;               // 8192 rows total
    float M = g_pm[r * SPLITS];
    #pragma unroll
    for (int j = 1; j < SPLITS; j++) M = fmaxf(M, g_pm[r * SPLITS + j]);
    float S = 0.0f;
    #pragma unroll
    for (int j = 0; j < SPLITS; j++)
        S += g_ps[r * SPLITS + j] * ex2f(g_pm[r * SPLITS + j] - M);
    float lse = LN2F * (M + log2f(S));
    sh[tid] = (double)(lse - g_poslogit[r]);
    __syncthreads();
    for (int o = 64; o > 0; o >>= 1) {
        if (tid < o) sh[tid] += sh[tid + o];
        __syncthreads();
    }
    if (tid == 0) g_part[blockIdx.x] = sh[0];
}

__global__ void reduce_final_kernel(float* __restrict__ out) {
    if (threadIdx.x == 0) {
        double acc = 0.0;
        #pragma unroll
        for (int i = 0; i < 64; i++) acc += g_part[i];
        out[0] = (float)(acc / (double)NQ);
    }
}

// ============================================================================
// kernel_launch
// ============================================================================
extern "C" void kernel_launch(void* const* d_in, const int* in_sizes, int n_in,
                              void* d_out, int out_size) {
    (void)n_in; (void)out_size;
    const float* a0 = (const float*)d_in[0];
    const float* a1 = (const float*)d_in[1];
    const float* a2 = (const float*)d_in[2];
    const float *q, *p, *neg;
    if (in_sizes[2] == NNEG * KD)      { q = a0; p = a1; neg = a2; }
    else if (in_sizes[1] == NNEG * KD) { q = a0; p = a2; neg = a1; }
    else                               { q = a1; p = a2; neg = a0; }

    cudaFuncSetAttribute(conloss_main_kernel,
                         cudaFuncAttributeMaxDynamicSharedMemorySize, SMEM_TOTAL);

    prep_neg_kernel<<<(NNEG * KD) / 1024, 256>>>(neg);
    prep_q_kernel<<<NQ / 8, 256>>>(q, p);
    conloss_main_kernel<<<dim3(NQ / MB, SPLITS), 256, SMEM_TOTAL>>>();
    reduce_partial_kernel<<<64, 128>>>();
    reduce_final_kernel<<<1, 32>>>((float*)d_out);
}